// round 1
// baseline (speedup 1.0000x reference)
#include <cuda_runtime.h>
#include <cstdint>

// Problem constants (fixed by the dataset)
#define B_ 512
#define T_ 2048
#define S_ 128
#define L_ 64
#define P_ (T_ - L_ + 1)   // 1985 sliding windows
#define THREADS 256

// Packed 2xfp32 FMA: d = a*b + d  (FFMA2 — only reachable via PTX fma.rn.f32x2)
__device__ __forceinline__ void fma_f32x2(unsigned long long& d,
                                          unsigned long long a,
                                          unsigned long long b) {
    asm("fma.rn.f32x2 %0, %1, %2, %0;" : "+l"(d) : "l"(a), "l"(b));
}

__device__ __forceinline__ float lo32(unsigned long long v) {
    return __uint_as_float((unsigned int)v);
}
__device__ __forceinline__ float hi32(unsigned long long v) {
    return __uint_as_float((unsigned int)(v >> 32));
}

// One block per batch sample b. 256 threads:
//   thread t handles shapelet s = t & 127, window half = t >> 7.
// Shapelet (64 floats) lives in 32 packed .b64 registers. Window values are
// broadcast LDS.64 reads (all lanes in a warp share the same p), so the smem
// crossbar cost is negligible and FFMA2 + LDS dual-flow saturates issue.
__global__ void __launch_bounds__(THREADS, 2)
shapelet_min_dist_kernel(const float* __restrict__ x,
                         const float* __restrict__ sh,
                         float* __restrict__ out) {
    // Phase-shared smem. Phase 1: shapelet staging [0, 128*66).
    // Phase 2 (after sync): xbuf[0,2048) | xshift[2048,4096) | p2c[4096,6144) | pmean[6144,8192)
    __shared__ __align__(16) float smf[8448];
    __shared__ float red[THREADS];

    const int tid = threadIdx.x;
    const int b = blockIdx.x;

    // ---- Phase 1: stage shapelets with stride 66 (8B-aligned rows, de-conflicted) ----
    for (int i = tid; i < S_ * L_; i += THREADS) {
        int ss = i >> 6;
        int ll = i & 63;
        smf[ss * 66 + ll] = sh[i];
    }
    __syncthreads();

    const int s = tid & (S_ - 1);
    const int half = tid >> 7;

    // Pull my shapelet into 32 packed registers; derive sum and squared norm.
    unsigned long long sh2[32];
    {
        const unsigned long long* sp =
            reinterpret_cast<const unsigned long long*>(smf + s * 66);
#pragma unroll
        for (int k = 0; k < 32; ++k) sh2[k] = sp[k];
    }
    float shsum = 0.f, s2 = 0.f;
#pragma unroll
    for (int k = 0; k < 32; ++k) {
        float a = lo32(sh2[k]), c = hi32(sh2[k]);
        shsum += a + c;
        s2 = fmaf(a, a, s2);
        s2 = fmaf(c, c, s2);
    }
    __syncthreads();  // done reading shapelet staging; smem is reused below

    float* xbuf = smf;          // x[b, :]
    float* xsh  = smf + 2048;   // x[b, i+1]  (8B-aligned pairs for odd windows)
    float* p2c  = smf + 4096;   // centered squared norm per window
    float* pmn  = smf + 6144;   // window mean

    // ---- Phase 2: load x row, build shifted copy ----
    const float* xg = x + (size_t)b * T_;
    for (int i = tid; i < T_; i += THREADS) xbuf[i] = xg[i];
    for (int i = tid; i < T_; i += THREADS) xsh[i] = (i + 1 < T_) ? xg[i + 1] : 0.f;
    __syncthreads();

    // ---- Window statistics: mean and centered squared norm ----
    for (int p = tid; p < P_; p += THREADS) {
        float sum = 0.f, sq = 0.f;
#pragma unroll 8
        for (int l = 0; l < L_; ++l) {
            float v = xbuf[p + l];
            sum += v;
            sq = fmaf(v, v, sq);
        }
        float mean = sum * (1.f / 64.f);
        p2c[p] = fmaf(-sum, mean, sq);   // sum(x^2) - 64*mean^2
        pmn[p] = mean;
    }
    __syncthreads();

    // ---- Main loop: min over windows of d2 = p2c + s2 - 2*dot + 2*mean*shsum ----
    const float shsum2 = 2.f * shsum;
    const int p0 = half ? 994 : 0;
    const int p1 = half ? P_ : 994;
    float mind = 3.4e38f;

    const unsigned long long* xe_base =
        reinterpret_cast<const unsigned long long*>(xbuf);
    const unsigned long long* xo_base =
        reinterpret_cast<const unsigned long long*>(xsh);

    for (int p = p0; p < p1; p += 2) {
        // p is even: window p pairs come from xbuf, window p+1 from the
        // shifted copy (both start at 8B-aligned double index p>>1).
        unsigned long long ae = 0ULL, ao = 0ULL;
        const unsigned long long* xe = xe_base + (p >> 1);
        const unsigned long long* xo = xo_base + (p >> 1);
#pragma unroll
        for (int k = 0; k < 32; ++k) {
            fma_f32x2(ae, xe[k], sh2[k]);
            fma_f32x2(ao, xo[k], sh2[k]);
        }
        float dot_e = lo32(ae) + hi32(ae);
        float dot_o = lo32(ao) + hi32(ao);

        float d2e = p2c[p] + s2 - 2.f * dot_e + pmn[p] * shsum2;
        mind = fminf(mind, d2e);
        if (p + 1 < p1) {
            float d2o = p2c[p + 1] + s2 - 2.f * dot_o + pmn[p + 1] * shsum2;
            mind = fminf(mind, d2o);
        }
    }

    // ---- Combine the two window-halves per shapelet, sqrt, store ----
    red[tid] = mind;
    __syncthreads();
    if (tid < 128) {
        float m = fminf(red[tid], red[tid + 128]);
        out[(size_t)b * S_ + tid] = sqrtf(fmaxf(m, 0.f));
    }
}

extern "C" void kernel_launch(void* const* d_in, const int* in_sizes, int n_in,
                              void* d_out, int out_size) {
    const float* x  = (const float*)d_in[0];   // (512, 1, 2048) fp32
    const float* sh = (const float*)d_in[1];   // (128, 1, 64)   fp32
    float* out = (float*)d_out;                // (512, 128)     fp32
    shapelet_min_dist_kernel<<<B_, THREADS>>>(x, sh, out);
}

// round 4
// speedup vs baseline: 5.0153x; 5.0153x over previous
#include <cuda_runtime.h>
#include <cstdint>

#define B_ 512
#define T_ 2048
#define S_ 128
#define P_ 1985
#define THREADS 512
#define BSTRIDE 68   // f32 stride for shapelet rows: (68*gid+tig)%32 all-distinct -> conflict-free

// smem float layout: xr[2176] | Bs[128*68] | p2c[2048] | s2[128] | wmin[256]
#define SMEM_FLOATS (2176 + 128 * BSTRIDE + 2048 + 128 + 256)
#define SMEM_BYTES  (SMEM_FLOATS * 4)

extern __shared__ float smf[];

static __device__ __forceinline__ float tf32r(float v) {
    float r;
    asm("cvt.rna.tf32.f32 %0, %1;" : "=f"(r) : "f"(v));
    return r;
}

// D = A*B + 0   (zero C via a single shared zero register)
static __device__ __forceinline__ void mma8_zc(float d[4],
        uint32_t a0, uint32_t a1, uint32_t a2, uint32_t a3,
        uint32_t b0, uint32_t b1) {
    asm volatile(
        "mma.sync.aligned.m16n8k8.row.col.f32.tf32.tf32.f32 "
        "{%0,%1,%2,%3}, {%4,%5,%6,%7}, {%8,%9}, {%10,%10,%10,%10};"
        : "=f"(d[0]), "=f"(d[1]), "=f"(d[2]), "=f"(d[3])
        : "r"(a0), "r"(a1), "r"(a2), "r"(a3), "r"(b0), "r"(b1), "f"(0.f));
}
// D = A*B + D
static __device__ __forceinline__ void mma8_acc(float d[4],
        uint32_t a0, uint32_t a1, uint32_t a2, uint32_t a3,
        uint32_t b0, uint32_t b1) {
    asm volatile(
        "mma.sync.aligned.m16n8k8.row.col.f32.tf32.tf32.f32 "
        "{%0,%1,%2,%3}, {%4,%5,%6,%7}, {%8,%9}, {%0,%1,%2,%3};"
        : "+f"(d[0]), "+f"(d[1]), "+f"(d[2]), "+f"(d[3])
        : "r"(a0), "r"(a1), "r"(a2), "r"(a3), "r"(b0), "r"(b1));
}

// One CTA per batch sample. 16 warps: wid>>3 = m-half (1024 windows),
// wid&7 = 16-shapelet column group. B fragments live in registers.
__global__ void __launch_bounds__(THREADS, 1)
shapelet_mma_kernel(const float* __restrict__ x,
                    const float* __restrict__ sh,
                    float* __restrict__ out) {
    float* xr   = smf;                       // x row, tf32-rounded, zero-padded to 2176
    float* Bs   = smf + 2176;                // centered shapelets (tf32-rounded), [128][68]
    float* p2c  = Bs + 128 * BSTRIDE;        // centered window sq-norm (fp32), 2048
    float* s2   = p2c + 2048;                // RAW shapelet sq-norm, 128
    float* wmin = s2 + 128;                  // per-half per-col partial mins, 2*128

    const int tid = threadIdx.x, b = blockIdx.x;
    const int wid = tid >> 5, lane = tid & 31;
    const int gid = lane >> 2, tig = lane & 3;

    // ---- x row (tf32-rounded so MMA and stats see the same values) ----
    const float* xg = x + (size_t)b * T_;
    for (int i = tid; i < 2176; i += THREADS)
        xr[i] = (i < T_) ? tf32r(xg[i]) : 0.f;

    // ---- centered shapelets -> smem (tf32-rounded); s2 = RAW squared norm ----
    // d2 = ||p_c||^2 + ||s_raw||^2 - 2*p_c.s  and  p_c.s == p_raw.s_c
    // (both centerings annihilate against the other factor's constant term).
    if (tid < S_) {
        const float* sp = sh + tid * 64;
        float sm = 0.f, q2raw = 0.f;
#pragma unroll
        for (int l = 0; l < 64; ++l) {
            float v = sp[l];
            sm += v;
            q2raw = fmaf(v, v, q2raw);
        }
        float mean = sm * (1.f / 64.f);
#pragma unroll
        for (int l = 0; l < 64; ++l)
            Bs[tid * BSTRIDE + l] = tf32r(sp[l] - mean);
        s2[tid] = q2raw;   // raw norm — includes the 64*mean^2 the reference keeps
    }
    __syncthreads();

    // ---- window stats: 4 windows/thread via sliding update ----
    {
        int p0 = tid * 4;
        float s = 0.f, qq = 0.f;
#pragma unroll
        for (int l = 0; l < 64; ++l) {
            float v = xr[p0 + l];
            s += v;
            qq = fmaf(v, v, qq);
        }
        p2c[p0] = (p0 < P_) ? fmaf(-s, s * (1.f / 64.f), qq) : 3.0e30f;
#pragma unroll
        for (int k = 1; k < 4; ++k) {
            float vo = xr[p0 + k - 1], vi = xr[p0 + 63 + k];
            s += vi - vo;
            qq += fmaf(vi, vi, -vo * vo);
            int p = p0 + k;
            p2c[p] = (p < P_) ? fmaf(-s, s * (1.f / 64.f), qq) : 3.0e30f;
        }
    }
    __syncthreads();

    // ---- persistent B fragments: 2 n-chunks x 8 k-chunks x 2 regs ----
    const int h = wid >> 3, q = wid & 7;
    const uint32_t* Bu = reinterpret_cast<const uint32_t*>(Bs);
    uint32_t Bf[2][8][2];
#pragma unroll
    for (int nc = 0; nc < 2; ++nc) {
        int row = q * 16 + nc * 8 + gid;
#pragma unroll
        for (int kc = 0; kc < 8; ++kc) {
            Bf[nc][kc][0] = Bu[row * BSTRIDE + kc * 8 + tig];
            Bf[nc][kc][1] = Bu[row * BSTRIDE + kc * 8 + tig + 4];
        }
    }

    float mn[2][2] = {{3.4e38f, 3.4e38f}, {3.4e38f, 3.4e38f}};
    const uint32_t* xu = reinterpret_cast<const uint32_t*>(xr);
    const int mstart = h * 1024;

    // ---- main loop: 64 groups of 16 windows ----
    for (int mg = 0; mg < 64; ++mg) {
        const int rbase = mstart + mg * 16 + gid;
        // 18 broadcast LDS feed all 16 MMAs of this m-group:
        // a0(kc)=v[2kc] (row gid, k=tig), a1=v[2kc+2] (row gid+8),
        // a2=v[2kc+1] (k=tig+4), a3=v[2kc+3]
        uint32_t v[18];
#pragma unroll
        for (int j = 0; j < 18; ++j) v[j] = xu[rbase + tig + 4 * j];
        float pc0 = p2c[rbase], pc1 = p2c[rbase + 8];
#pragma unroll
        for (int nc = 0; nc < 2; ++nc) {
            float acc[4];
            mma8_zc(acc, v[0], v[2], v[1], v[3], Bf[nc][0][0], Bf[nc][0][1]);
#pragma unroll
            for (int kc = 1; kc < 8; ++kc)
                mma8_acc(acc, v[2 * kc], v[2 * kc + 2], v[2 * kc + 1],
                         v[2 * kc + 3], Bf[nc][kc][0], Bf[nc][kc][1]);
            // d2-s2 = pc - 2*dot ; fold min over both fragment rows
            mn[nc][0] = fminf(mn[nc][0],
                              fminf(fmaf(acc[0], -2.f, pc0), fmaf(acc[2], -2.f, pc1)));
            mn[nc][1] = fminf(mn[nc][1],
                              fminf(fmaf(acc[1], -2.f, pc0), fmaf(acc[3], -2.f, pc1)));
        }
    }

    // ---- reduce over the 8 row-groups (lanes with same tig) ----
#pragma unroll
    for (int nc = 0; nc < 2; ++nc)
#pragma unroll
        for (int e = 0; e < 2; ++e) {
            float m = mn[nc][e];
            m = fminf(m, __shfl_xor_sync(0xffffffffu, m, 4));
            m = fminf(m, __shfl_xor_sync(0xffffffffu, m, 8));
            m = fminf(m, __shfl_xor_sync(0xffffffffu, m, 16));
            if (lane < 4)
                wmin[h * 128 + q * 16 + nc * 8 + lane * 2 + e] = m;
        }
    __syncthreads();

    // ---- combine m-halves, add s2, sqrt, store ----
    if (tid < S_) {
        float d2 = fminf(wmin[tid], wmin[128 + tid]) + s2[tid];
        out[(size_t)b * S_ + tid] = sqrtf(fmaxf(d2, 0.f));
    }
}

extern "C" void kernel_launch(void* const* d_in, const int* in_sizes, int n_in,
                              void* d_out, int out_size) {
    const float* x  = (const float*)d_in[0];   // (512, 1, 2048) fp32
    const float* sh = (const float*)d_in[1];   // (128, 1, 64)   fp32
    float* out = (float*)d_out;                // (512, 128)     fp32
    cudaFuncSetAttribute(shapelet_mma_kernel,
                         cudaFuncAttributeMaxDynamicSharedMemorySize, SMEM_BYTES);
    shapelet_mma_kernel<<<B_, THREADS, SMEM_BYTES>>>(x, sh, out);
}